// round 10
// baseline (speedup 1.0000x reference)
#include <cuda_runtime.h>
#include <cuda.h>
#include <cuda_bf16.h>
#include <stdint.h>
#include <math.h>

typedef unsigned int u32;
typedef unsigned short u16;
typedef unsigned long long u64t;

// Fixed problem shape
#define NROWS 8192
#define DIM   128
#define BCLS  64
#define RBLK  128
#define NRB   (NROWS/RBLK)     // 64 row blocks
#define NTILE_TOT 2080         // upper-tri pairs incl diagonal: 64*65/2
#define NT_PER_BLK 16
#define NGRID (NTILE_TOT/NT_PER_BLK)   // 130 blocks
#define NBUF  4
#define TILEB 16384            // fp8 tile: 128 rows x 128B
#define SLOTB (2*TILEB)        // A+B pair per slot

__device__ __align__(256) unsigned char g_feat8[NROWS * DIM];   // normalized e4m3
__device__ __align__(64) CUtensorMap g_mapF;
// per-tile partial sums (overwritten fully every run; no zero-init needed)
__device__ float g_trA[NTILE_TOT][2][RBLK];   // row-side sum(all), per cg half
__device__ float g_trP[NTILE_TOT][2][RBLK];   // row-side sum(pos)
__device__ float g_tcA[NTILE_TOT][8][RBLK];   // col-side sum(all), per rg warp
__device__ float g_tcP[NTILE_TOT][8][RBLK];   // col-side sum(pos)
__device__ float g_partial[NRB];

__device__ __host__ __forceinline__ int tri(int I) { return I * 64 - ((I * (I - 1)) >> 1); }

// ---------------------------------------------------------------------------
// PTX helpers
// ---------------------------------------------------------------------------
__device__ __forceinline__ u32 smem_u32(const void* p) {
    return (u32)__cvta_generic_to_shared(p);
}
__device__ __forceinline__ void mbar_init(u32 addr, u32 cnt) {
    asm volatile("mbarrier.init.shared.b64 [%0], %1;" :: "r"(addr), "r"(cnt) : "memory");
}
__device__ __forceinline__ void mbar_expect(u32 addr, u32 bytes) {
    asm volatile("mbarrier.arrive.expect_tx.shared.b64 _, [%0], %1;"
                 :: "r"(addr), "r"(bytes) : "memory");
}
__device__ __forceinline__ void mbar_arrive(u32 addr) {
    asm volatile("mbarrier.arrive.shared.b64 _, [%0];" :: "r"(addr) : "memory");
}
__device__ __forceinline__ void mbar_wait(u32 addr, u32 parity) {
    asm volatile("{\n\t.reg .pred P1;\n\t"
                 "WAIT_LP_%=:\n\t"
                 "mbarrier.try_wait.parity.acquire.cta.shared::cta.b64 P1, [%0], %1, 0x989680;\n\t"
                 "@P1 bra.uni WAIT_DN_%=;\n\t"
                 "bra.uni WAIT_LP_%=;\n\t"
                 "WAIT_DN_%=:\n\t}"
                 :: "r"(addr), "r"(parity) : "memory");
}
__device__ __forceinline__ void tma2d(u32 dst, const void* map, int cx, int cy, u32 mbar) {
    asm volatile("cp.async.bulk.tensor.2d.shared::cta.global.tile.mbarrier::complete_tx::bytes "
                 "[%0], [%1, {%2, %3}], [%4];"
                 :: "r"(dst), "l"(map), "r"(cx), "r"(cy), "r"(mbar) : "memory");
}
__device__ __forceinline__ void ldsm4(u32& q0, u32& q1, u32& q2, u32& q3, u32 addr) {
    asm volatile("ldmatrix.sync.aligned.m8n8.x4.shared.b16 {%0,%1,%2,%3}, [%4];"
                 : "=r"(q0), "=r"(q1), "=r"(q2), "=r"(q3) : "r"(addr));
}
__device__ __forceinline__ void mma_fp8(float* dacc, u32 qa0, u32 qa1, u32 qa2, u32 qa3,
                                        u32 qb0, u32 qb1) {
    asm volatile("mma.sync.aligned.m16n8k32.row.col.f32.e4m3.e4m3.f32 "
                 "{%0,%1,%2,%3}, {%4,%5,%6,%7}, {%8,%9}, {%0,%1,%2,%3};"
                 : "+f"(dacc[0]), "+f"(dacc[1]), "+f"(dacc[2]), "+f"(dacc[3])
                 : "r"(qa0), "r"(qa1), "r"(qa2), "r"(qa3), "r"(qb0), "r"(qb1));
}
__device__ __forceinline__ float ex2f(float v) {
    float r;
    asm("ex2.approx.f32 %0, %1;" : "=f"(r) : "f"(v));
    return r;
}

// ---------------------------------------------------------------------------
// Kernel 1: L2-normalize rows (fp32 math), emit e4m3 [8192][128]
// ---------------------------------------------------------------------------
__global__ __launch_bounds__(256) void normalize_kernel(const float* __restrict__ x) {
    int gw   = (blockIdx.x * 256 + threadIdx.x) >> 5;
    int lane = threadIdx.x & 31;
    float4 v = ((const float4*)(x + (size_t)gw * DIM))[lane];
    float ss = v.x * v.x + v.y * v.y + v.z * v.z + v.w * v.w;
    #pragma unroll
    for (int o = 16; o; o >>= 1) ss += __shfl_xor_sync(0xffffffffu, ss, o);
    float inv = 1.0f / fmaxf(sqrtf(ss), 1e-12f);
    u16 p01, p23;
    asm("cvt.rn.satfinite.e4m3x2.f32 %0, %1, %2;" : "=h"(p01)
        : "f"(v.y * inv), "f"(v.x * inv));
    asm("cvt.rn.satfinite.e4m3x2.f32 %0, %1, %2;" : "=h"(p23)
        : "f"(v.w * inv), "f"(v.z * inv));
    u32 word = (u32)p01 | ((u32)p23 << 16);
    ((u32*)(g_feat8 + (size_t)gw * DIM))[lane] = word;
}

// ---------------------------------------------------------------------------
// Kernel 2: symmetric fused fp8 kernel. 130 blocks x 16 tiles each over the
// 2080 upper-triangular (I,J) 128x128 tile pairs. Per tile: TMA-load A(I),
// B(J); mma E = exp(sim-1); row-side sums for I (always), col-side sums for
// J (off-diagonal only, E[i,j]=E[j,i]). Partials -> global scratch (no
// atomics). 512 threads = 16 warps: rg = w>>1 (16 rows), cg = w&1 (64 cols).
// ---------------------------------------------------------------------------
__global__ __launch_bounds__(512, 1) void fused_sym_kernel(const int* __restrict__ y) {
    extern __shared__ __align__(1024) char smem[];
    const u32 sRing = smem_u32(smem);          // 4 slots x 32KB (A+B)

    __shared__ __align__(8) u64t full_sh[NBUF];
    __shared__ __align__(8) u64t rel_sh[NBUF];
    __shared__ int ysm[BCLS];

    const int tid  = threadIdx.x;
    const int lane = tid & 31;
    const int w    = tid >> 5;
    const int rg   = w >> 1;
    const int cg   = w & 1;
    const int n0   = blockIdx.x * NT_PER_BLK;

    u32 fullb[NBUF], relb[NBUF];
    #pragma unroll
    for (int i = 0; i < NBUF; i++) {
        fullb[i] = smem_u32(&full_sh[i]);
        relb[i]  = smem_u32(&rel_sh[i]);
    }

    if (tid < BCLS) ysm[tid] = y[tid];
    if (tid == 0) {
        #pragma unroll
        for (int i = 0; i < NBUF; i++) { mbar_init(fullb[i], 1); mbar_init(relb[i], 16); }
    }
    __syncthreads();

    // tile iterator: n0 -> (I, J)
    int I = 0;
    while (tri(I + 1) <= n0) I++;
    int J = I + (n0 - tri(I));

    const CUtensorMap* mp = &g_mapF;
    if (tid == 0) {
        asm volatile("prefetch.tensormap [%0];" :: "l"(mp));
        int pI = I, pJ = J;
        #pragma unroll
        for (int s = 0; s < NBUF; s++) {
            u32 dst = sRing + (u32)(s * SLOTB);
            mbar_expect(fullb[s], SLOTB);
            tma2d(dst,         mp, 0, pI * RBLK, fullb[s]);
            tma2d(dst + TILEB, mp, 0, pJ * RBLK, fullb[s]);
            pJ++; if (pJ == NRB) { pI++; pJ = pI; }
        }
    }

    // ldmatrix addressing (fp8, 128B rows)
    const int lrow  = lane & 15;
    const u32 hi    = (u32)(lane >> 4);
    const u32 sw    = (u32)(lrow & 7);
    const u32 offA  = (u32)((rg * 16 + lrow) * 128);
    const u32 baseB = (u32)((cg * 64 + lrow) * 128);
    const int r0l   = rg * 16 + (lane >> 2);        // this thread's local row
    const int l3    = lane & 3;
    const float L2E = 1.4426950408889634f;

    // producer prefetch iterator (only tid 0 uses)
    int pI2 = I, pJ2 = J;
    #pragma unroll
    for (int s = 0; s < NBUF; s++) { pJ2++; if (pJ2 == NRB) { pI2++; pJ2 = pI2; } }

    for (int t = 0; t < NT_PER_BLK; t++) {
        const int n = n0 + t;
        const int slot = t & (NBUF - 1);
        mbar_wait(fullb[slot], (u32)((t >> 2) & 1));
        const u32 sA = sRing + (u32)(slot * SLOTB);
        const u32 sB = sA + TILEB;

        const int clsI = ysm[I];
        const int clsJ = ysm[J];
        const bool diag = (I == J);

        // row-side mask bits (16 cols), col-side mask floats (2 rows)
        u32 mrb0 = 0, mrb1 = 0;
        #pragma unroll
        for (int nb = 0; nb < 8; nb++) {
            int c0 = nb * 8 + 2 * l3;
            if (ysm[c0]     == clsI) mrb0 |= 1u << nb;
            if (ysm[c0 + 1] == clsI) mrb1 |= 1u << nb;
        }
        const float mc0 = (clsJ == ysm[r0l & 63])       ? 1.0f : 0.0f;
        const float mc1 = (clsJ == ysm[(r0l + 8) & 63]) ? 1.0f : 0.0f;

        // MMA: acc[8][4]
        float acc[8][4];
        #pragma unroll
        for (int nb = 0; nb < 8; nb++) {
            #pragma unroll
            for (int q = 0; q < 4; q++) acc[nb][q] = 0.f;
        }
        #pragma unroll
        for (int s = 0; s < 4; s++) {
            const u32 ch = (u32)(2 * s) + hi;
            const u32 so = (ch ^ sw) << 4;
            u32 qa0, qa1, qa2, qa3;
            ldsm4(qa0, qa1, qa2, qa3, sA + offA + so);
            #pragma unroll
            for (int pp = 0; pp < 4; pp++) {
                u32 qb0, qb1, qb2, qb3;
                ldsm4(qb0, qb1, qb2, qb3, sB + baseB + (u32)(pp * 2048) + so);
                mma_fp8(acc[2 * pp],     qa0, qa1, qa2, qa3, qb0, qb2);
                mma_fp8(acc[2 * pp + 1], qa0, qa1, qa2, qa3, qb1, qb3);
            }
        }
        if (lane == 0) mbar_arrive(relb[slot]);   // done reading this slot

        // epilogue
        float ra0 = 0.f, ra1 = 0.f, rp0 = 0.f, rp1 = 0.f;
        float ca[16], cp[16];
        #pragma unroll
        for (int i = 0; i < 16; i++) { ca[i] = 0.f; cp[i] = 0.f; }

        #pragma unroll
        for (int nb = 0; nb < 8; nb++) {
            float e0 = ex2f(fmaf(acc[nb][0], L2E, -L2E));
            float e1 = ex2f(fmaf(acc[nb][1], L2E, -L2E));
            float e2 = ex2f(fmaf(acc[nb][2], L2E, -L2E));
            float e3 = ex2f(fmaf(acc[nb][3], L2E, -L2E));
            float m0 = (float)((mrb0 >> nb) & 1);
            float m1 = (float)((mrb1 >> nb) & 1);
            ra0 += e0 + e1;
            ra1 += e2 + e3;
            rp0 = fmaf(e0, m0, fmaf(e1, m1, rp0));
            rp1 = fmaf(e2, m0, fmaf(e3, m1, rp1));
            if (!diag) {
                ca[2 * nb]     += e0 + e2;
                ca[2 * nb + 1] += e1 + e3;
                cp[2 * nb]     = fmaf(e0, mc0, fmaf(e2, mc1, cp[2 * nb]));
                cp[2 * nb + 1] = fmaf(e1, mc0, fmaf(e3, mc1, cp[2 * nb + 1]));
            }
        }

        // row-side flush: quad reduce, lane&3==0 stores
        #pragma unroll
        for (int o = 1; o <= 2; o <<= 1) {
            ra0 += __shfl_xor_sync(0xffffffffu, ra0, o);
            ra1 += __shfl_xor_sync(0xffffffffu, ra1, o);
            rp0 += __shfl_xor_sync(0xffffffffu, rp0, o);
            rp1 += __shfl_xor_sync(0xffffffffu, rp1, o);
        }
        if (l3 == 0) {
            g_trA[n][cg][r0l]     = ra0;
            g_trP[n][cg][r0l]     = rp0;
            g_trA[n][cg][r0l + 8] = ra1;
            g_trP[n][cg][r0l + 8] = rp1;
        }

        // col-side flush: reduce across lane>>2 (xor 4,8,16), lanes 0..3 store
        if (!diag) {
            #pragma unroll
            for (int o = 4; o <= 16; o <<= 1) {
                #pragma unroll
                for (int i = 0; i < 16; i++) {
                    ca[i] += __shfl_xor_sync(0xffffffffu, ca[i], o);
                    cp[i] += __shfl_xor_sync(0xffffffffu, cp[i], o);
                }
            }
            if (lane < 4) {
                #pragma unroll
                for (int nb = 0; nb < 8; nb++) {
                    int jl0 = cg * 64 + nb * 8 + 2 * lane;
                    g_tcA[n][rg][jl0]     = ca[2 * nb];
                    g_tcP[n][rg][jl0]     = cp[2 * nb];
                    g_tcA[n][rg][jl0 + 1] = ca[2 * nb + 1];
                    g_tcP[n][rg][jl0 + 1] = cp[2 * nb + 1];
                }
            }
        }

        // producer: prefetch tile t+NBUF into this slot
        if (tid == 0 && t + NBUF < NT_PER_BLK) {
            mbar_wait(relb[slot], (u32)((t >> 2) & 1));
            u32 dst = sRing + (u32)(slot * SLOTB);
            mbar_expect(fullb[slot], SLOTB);
            tma2d(dst,         mp, 0, pI2 * RBLK, fullb[slot]);
            tma2d(dst + TILEB, mp, 0, pJ2 * RBLK, fullb[slot]);
            pJ2++; if (pJ2 == NRB) { pI2++; pJ2 = pI2; }
        }

        // advance tile iterator
        J++; if (J == NRB) { I++; J = I; }
    }
}

// ---------------------------------------------------------------------------
// Kernel 3: assemble per-row sums from tile partials, per-row loss,
// block-reduce to per-rowblock partial. Deterministic (fixed order).
// ---------------------------------------------------------------------------
__global__ __launch_bounds__(128) void loss_kernel() {
    __shared__ float red[128];
    const int rb = blockIdx.x;
    const int il = threadIdx.x;

    float all = 0.f, pos = 0.f;
    // row-side: tiles (rb, J) for J = rb..63
    const int base = tri(rb);
    for (int k = 0; k < NRB - rb; k++) {
        all += g_trA[base + k][0][il] + g_trA[base + k][1][il];
        pos += g_trP[base + k][0][il] + g_trP[base + k][1][il];
    }
    // col-side: tiles (I, rb) for I = 0..rb-1
    for (int i2 = 0; i2 < rb; i2++) {
        int nn = tri(i2) + rb - i2;
        #pragma unroll
        for (int g = 0; g < 8; g++) {
            all += g_tcA[nn][g][il];
            pos += g_tcP[nn][g][il];
        }
    }
    red[il] = -logf(pos / (all + 1e-8f) + 1e-8f);
    __syncthreads();
    #pragma unroll
    for (int o = 64; o; o >>= 1) {
        if (il < o) red[il] += red[il + o];
        __syncthreads();
    }
    if (il == 0) g_partial[rb] = red[0];
}

__global__ void final_kernel(float* __restrict__ out) {
    float s = 0.f;
    #pragma unroll
    for (int i = 0; i < NRB; i++) s += g_partial[i];
    out[0] = s / (float)NROWS;
}

// ---------------------------------------------------------------------------
// Host
// ---------------------------------------------------------------------------
typedef CUresult (*EncFn)(CUtensorMap*, CUtensorMapDataType, cuuint32_t, void*,
                          const cuuint64_t*, const cuuint64_t*, const cuuint32_t*,
                          const cuuint32_t*, CUtensorMapInterleave, CUtensorMapSwizzle,
                          CUtensorMapL2promotion, CUtensorMapFloatOOBfill);

extern "C" void kernel_launch(void* const* d_in, const int* in_sizes, int n_in,
                              void* d_out, int out_size) {
    const float* x = (const float*)d_in[0];   // [64,128,128] f32
    const int*   y = (const int*)d_in[1];     // [64] i32
    float* out = (float*)d_out;

    static CUtensorMap h_map;
    static int inited = 0;
    const int dyn_smem = NBUF * SLOTB;         // 128 KB
    if (!inited) {
        cudaFuncSetAttribute(fused_sym_kernel,
                             cudaFuncAttributeMaxDynamicSharedMemorySize, dyn_smem);
        void* fptr = 0;
        cudaDriverEntryPointQueryResult qr;
        cudaGetDriverEntryPoint("cuTensorMapEncodeTiled", &fptr,
                                cudaEnableDefault, &qr);
        void* dfeat = 0;
        cudaGetSymbolAddress(&dfeat, g_feat8);
        cuuint64_t dims[2]    = {DIM, NROWS};
        cuuint64_t strides[1] = {DIM};
        cuuint32_t box[2]     = {DIM, RBLK};
        cuuint32_t es[2]      = {1, 1};
        ((EncFn)fptr)(&h_map, CU_TENSOR_MAP_DATA_TYPE_UINT8, 2, dfeat,
                      dims, strides, box, es,
                      CU_TENSOR_MAP_INTERLEAVE_NONE, CU_TENSOR_MAP_SWIZZLE_128B,
                      CU_TENSOR_MAP_L2_PROMOTION_L2_128B,
                      CU_TENSOR_MAP_FLOAT_OOB_FILL_NONE);
        inited = 1;
    }

    cudaMemcpyToSymbolAsync(g_mapF, &h_map, sizeof(CUtensorMap), 0,
                            cudaMemcpyHostToDevice, 0);
    normalize_kernel<<<NROWS / 8, 256>>>(x);
    fused_sym_kernel<<<NGRID, 512, dyn_smem>>>(y);
    loss_kernel<<<NRB, 128>>>();
    final_kernel<<<1, 1>>>(out);
}

// round 11
// speedup vs baseline: 1.1668x; 1.1668x over previous
#include <cuda_runtime.h>
#include <cuda_bf16.h>
#include <stdint.h>
#include <math.h>

typedef unsigned int u32;

// Fixed problem shape
#define NROWS 8192
#define DIM   128
#define BCLS  64
#define RBLK  128
#define CTILE 128
#define NCHALF 2
#define CHALF (NROWS/NCHALF)           // 4096
#define NTILES (CHALF/CTILE)           // 32
#define NBLK  128                      // must be <= SM count (co-resident)

__device__ __align__(256) __nv_bfloat16 g_featb[NROWS * DIM];   // normalized bf16
__device__ float g_all[NCHALF][NROWS];
__device__ float g_pos[NCHALF][NROWS];
__device__ int g_ctr;                  // monotonic grid-barrier counter (init 0)

// ---------------------------------------------------------------------------
// PTX helpers
// ---------------------------------------------------------------------------
__device__ __forceinline__ u32 smem_u32(const void* p) {
    return (u32)__cvta_generic_to_shared(p);
}
__device__ __forceinline__ void cp16(u32 dst, const void* src) {
    asm volatile("cp.async.cg.shared.global [%0], [%1], 16;\n" :: "r"(dst), "l"(src));
}
__device__ __forceinline__ void cp_commit() {
    asm volatile("cp.async.commit_group;\n" ::: "memory");
}
template <int N>
__device__ __forceinline__ void cp_wait() {
    asm volatile("cp.async.wait_group %0;\n" :: "n"(N) : "memory");
}
__device__ __forceinline__ void ldsm4(u32& q0, u32& q1, u32& q2, u32& q3, u32 addr) {
    asm volatile("ldmatrix.sync.aligned.m8n8.x4.shared.b16 {%0,%1,%2,%3}, [%4];"
                 : "=r"(q0), "=r"(q1), "=r"(q2), "=r"(q3) : "r"(addr));
}
__device__ __forceinline__ void mma16816(float* dacc, u32 qa0, u32 qa1,
                                         u32 qa2, u32 qa3, u32 qb0, u32 qb1) {
    asm volatile("mma.sync.aligned.m16n8k16.row.col.f32.bf16.bf16.f32 "
                 "{%0,%1,%2,%3}, {%4,%5,%6,%7}, {%8,%9}, {%0,%1,%2,%3};"
                 : "+f"(dacc[0]), "+f"(dacc[1]), "+f"(dacc[2]), "+f"(dacc[3])
                 : "r"(qa0), "r"(qa1), "r"(qa2), "r"(qa3), "r"(qb0), "r"(qb1));
}

// Re-entrant grid barrier: monotonic counter, generation arithmetic.
// Safe because all NBLK blocks are co-resident (NBLK <= SM count).
__device__ __forceinline__ void grid_barrier() {
    __syncthreads();
    if (threadIdx.x == 0) {
        __threadfence();
        int t = atomicAdd(&g_ctr, 1);
        int target = (t / NBLK + 1) * NBLK;
        while (atomicAdd(&g_ctr, 0) < target) { __nanosleep(64); }
        __threadfence();
    }
    __syncthreads();
}

// Tile loader: 128 rows x 128 bf16 (256B/row) -> smem, XOR-16B-chunk swizzle.
__device__ __forceinline__ void load_tile(u32 sbase,
                                          const __nv_bfloat16* gbase, int tid) {
    #pragma unroll
    for (int i = 0; i < 8; i++) {
        int id = i * 256 + tid;
        int r  = id >> 4;
        int c  = id & 15;
        u32 dst = sbase + r * 256 + ((c ^ (r & 7)) << 4);
        cp16(dst, (const char*)gbase + r * 256 + c * 16);
    }
}

// ---------------------------------------------------------------------------
// ONE kernel: normalize -> barrier -> fused sim/exp/masked-sums -> barrier ->
// finalize. 128 blocks x 256 threads. Block b: phase1 rows b*64..b*64+63;
// phase2 (chalf = b>>6, rowblk = b&63) as the proven R4 mainloop.
// ---------------------------------------------------------------------------
__global__ __launch_bounds__(256) void mono_kernel(const float* __restrict__ x,
                                                   const int* __restrict__ y,
                                                   float* __restrict__ out) {
    extern __shared__ __align__(1024) char smem[];
    __shared__ int ys[BCLS];
    __shared__ float red[256];

    const int tid  = threadIdx.x;
    const int lane = tid & 31;
    const int w    = tid >> 5;
    const int b    = blockIdx.x;

    // ---------------- Phase 1: normalize 64 rows per block -----------------
    #pragma unroll
    for (int i = 0; i < 8; i++) {
        int row = b * 64 + w * 8 + i;
        float4 v = ((const float4*)(x + (size_t)row * DIM))[lane];
        float ss = v.x * v.x + v.y * v.y + v.z * v.z + v.w * v.w;
        #pragma unroll
        for (int o = 16; o; o >>= 1) ss += __shfl_xor_sync(0xffffffffu, ss, o);
        float inv = 1.0f / fmaxf(sqrtf(ss), 1e-12f);
        __nv_bfloat162 p0 = __floats2bfloat162_rn(v.x * inv, v.y * inv);
        __nv_bfloat162 p1 = __floats2bfloat162_rn(v.z * inv, v.w * inv);
        __nv_bfloat162* dst = (__nv_bfloat162*)(g_featb + (size_t)row * DIM);
        dst[lane * 2 + 0] = p0;
        dst[lane * 2 + 1] = p1;
    }

    grid_barrier();

    // ---------------- Phase 2: fused mainloop (R4) -------------------------
    const u32 sA  = smem_u32(smem);
    const u32 sB0 = sA + 32768;
    const u32 sB1 = sA + 65536;
    const int rowblk = b & 63;
    const int chalf  = b >> 6;
    const int myclass = __ldg(y + rowblk);   // one class per 128-row block

    load_tile(sA,  g_featb + (size_t)rowblk * RBLK * DIM, tid);
    load_tile(sB0, g_featb + (size_t)(chalf * CHALF) * DIM, tid);
    cp_commit();
    if (tid < BCLS) ys[tid] = y[tid];
    __syncthreads();

    // col masks: col%64 periodic; thread's cols per n-tile nt: nt*8+2*(lane&3){+1}
    unsigned m0bits = 0, m1bits = 0;
    #pragma unroll
    for (int nt = 0; nt < 16; nt++) {
        int j0 = nt * 8 + 2 * (lane & 3);
        if (ys[j0 & 63]       == myclass) m0bits |= 1u << nt;
        if (ys[(j0 + 1) & 63] == myclass) m1bits |= 1u << nt;
    }

    // ldmatrix addressing
    const int lr = (lane & 7) | (((lane >> 3) & 1) << 3);
    const int hi = lane >> 4;
    const u32 kE = (u32)((lr & 6) << 4);
    const u32 ob = (u32)((hi ^ (lr & 1)) << 4);
    const u32 QA  = sA  + (u32)(w * 16 + lr) * 256 + ob;
    const u32 QB0 = sB0 + (u32)lr * 256 + ob;
    const u32 QB1 = sB1 + (u32)lr * 256 + ob;

    float sAll0 = 0.f, sAll1 = 0.f, sPos0 = 0.f, sPos1 = 0.f;

    for (int t = 0; t < NTILES; t++) {
        if (t + 1 < NTILES) {
            u32 sBnext = (t & 1) ? sB0 : sB1;
            load_tile(sBnext,
                      g_featb + (size_t)(chalf * CHALF + (t + 1) * CTILE) * DIM, tid);
            cp_commit();
            cp_wait<1>();
        } else {
            cp_wait<0>();
        }
        __syncthreads();

        float acc[16][4];
        #pragma unroll
        for (int i = 0; i < 16; i++) {
            #pragma unroll
            for (int j = 0; j < 4; j++) acc[i][j] = 0.f;
        }

        const u32 QB = (t & 1) ? QB1 : QB0;

        #pragma unroll
        for (int s = 0; s < 8; s++) {
            const u32 off = ((u32)(s << 5)) ^ kE;
            u32 qa0, qa1, qa2, qa3;
            ldsm4(qa0, qa1, qa2, qa3, QA + off);
            #pragma unroll
            for (int p = 0; p < 8; p++) {
                u32 qn0, qn1, qn2, qn3;
                ldsm4(qn0, qn1, qn2, qn3, QB + (u32)(p * 4096) + off);
                mma16816(acc[2 * p],     qa0, qa1, qa2, qa3, qn0, qn2);
                mma16816(acc[2 * p + 1], qa0, qa1, qa2, qa3, qn1, qn3);
            }
        }

        #pragma unroll
        for (int nt = 0; nt < 16; nt++) {
            float e0 = __expf(acc[nt][0] - 1.0f);
            float e1 = __expf(acc[nt][1] - 1.0f);
            float e2 = __expf(acc[nt][2] - 1.0f);
            float e3 = __expf(acc[nt][3] - 1.0f);
            sAll0 += e0 + e1;
            sAll1 += e2 + e3;
            if ((m0bits >> nt) & 1) { sPos0 += e0; sPos1 += e2; }
            if ((m1bits >> nt) & 1) { sPos0 += e1; sPos1 += e3; }
        }
        __syncthreads();
    }

    #pragma unroll
    for (int o = 1; o <= 2; o <<= 1) {
        sAll0 += __shfl_xor_sync(0xffffffffu, sAll0, o);
        sAll1 += __shfl_xor_sync(0xffffffffu, sAll1, o);
        sPos0 += __shfl_xor_sync(0xffffffffu, sPos0, o);
        sPos1 += __shfl_xor_sync(0xffffffffu, sPos1, o);
    }
    if ((lane & 3) == 0) {
        int g  = lane >> 2;
        int r0 = rowblk * RBLK + w * 16 + g;
        g_all[chalf][r0]     = sAll0;
        g_pos[chalf][r0]     = sPos0;
        g_all[chalf][r0 + 8] = sAll1;
        g_pos[chalf][r0 + 8] = sPos1;
    }

    grid_barrier();

    // ---------------- Phase 3: finalize (block 0) --------------------------
    if (b == 0) {
        float s = 0.f;
        #pragma unroll
        for (int i = 0; i < 32; i++) {
            int r = i * 256 + tid;
            float all = g_all[0][r] + g_all[1][r];
            float pos = g_pos[0][r] + g_pos[1][r];
            s += -logf(pos / (all + 1e-8f) + 1e-8f);
        }
        red[tid] = s;
        __syncthreads();
        #pragma unroll
        for (int o = 128; o; o >>= 1) {
            if (tid < o) red[tid] += red[tid + o];
            __syncthreads();
        }
        if (tid == 0) out[0] = red[0] / (float)NROWS;
    }
}

extern "C" void kernel_launch(void* const* d_in, const int* in_sizes, int n_in,
                              void* d_out, int out_size) {
    const float* x = (const float*)d_in[0];   // [64,128,128] f32
    const int*   y = (const int*)d_in[1];     // [64] i32
    float* out = (float*)d_out;

    static int attr_set = 0;
    const int dyn_smem = 96 * 1024;
    if (!attr_set) {
        cudaFuncSetAttribute(mono_kernel,
                             cudaFuncAttributeMaxDynamicSharedMemorySize, dyn_smem);
        attr_set = 1;
    }

    mono_kernel<<<NBLK, 256, dyn_smem>>>(x, y, out);
}

// round 12
// speedup vs baseline: 1.2219x; 1.0472x over previous
#include <cuda_runtime.h>
#include <cuda_bf16.h>
#include <stdint.h>
#include <math.h>

typedef unsigned int u32;

// Fixed problem shape
#define NROWS 8192
#define DIM   128
#define BCLS  64
#define RBLK  128
#define CTILE 128
#define NCHALF 2
#define CHALF (NROWS/NCHALF)           // 4096
#define NTILES (CHALF/CTILE)           // 32
#define NBLK  128                      // co-resident (<= SM count)
#define NTHR  512

__device__ __align__(256) __nv_bfloat16 g_featb[NROWS * DIM];
__device__ float g_all[NCHALF][4][NROWS];   // per column-group partials
__device__ float g_pos[NCHALF][4][NROWS];
__device__ int g_ctr;                        // monotonic barrier counter

// ---------------------------------------------------------------------------
// PTX helpers
// ---------------------------------------------------------------------------
__device__ __forceinline__ u32 smem_u32(const void* p) {
    return (u32)__cvta_generic_to_shared(p);
}
__device__ __forceinline__ void cp16(u32 dst, const void* src) {
    asm volatile("cp.async.cg.shared.global [%0], [%1], 16;\n" :: "r"(dst), "l"(src));
}
__device__ __forceinline__ void cp_commit() {
    asm volatile("cp.async.commit_group;\n" ::: "memory");
}
template <int N>
__device__ __forceinline__ void cp_wait() {
    asm volatile("cp.async.wait_group %0;\n" :: "n"(N) : "memory");
}
__device__ __forceinline__ void ldsm4(u32& q0, u32& q1, u32& q2, u32& q3, u32 addr) {
    asm volatile("ldmatrix.sync.aligned.m8n8.x4.shared.b16 {%0,%1,%2,%3}, [%4];"
                 : "=r"(q0), "=r"(q1), "=r"(q2), "=r"(q3) : "r"(addr));
}
__device__ __forceinline__ void mma16816(float* dacc, u32 qa0, u32 qa1,
                                         u32 qa2, u32 qa3, u32 qb0, u32 qb1) {
    asm volatile("mma.sync.aligned.m16n8k16.row.col.f32.bf16.bf16.f32 "
                 "{%0,%1,%2,%3}, {%4,%5,%6,%7}, {%8,%9}, {%0,%1,%2,%3};"
                 : "+f"(dacc[0]), "+f"(dacc[1]), "+f"(dacc[2]), "+f"(dacc[3])
                 : "r"(qa0), "r"(qa1), "r"(qa2), "r"(qa3), "r"(qb0), "r"(qb1));
}
__device__ __forceinline__ float ex2f(float v) {
    float r;
    asm("ex2.approx.f32 %0, %1;" : "=f"(r) : "f"(v));
    return r;
}

// Re-entrant grid barrier (all NBLK blocks co-resident).
__device__ __forceinline__ void grid_barrier() {
    __syncthreads();
    if (threadIdx.x == 0) {
        __threadfence();
        int t = atomicAdd(&g_ctr, 1);
        int target = (t / NBLK + 1) * NBLK;
        while (atomicAdd(&g_ctr, 0) < target) { __nanosleep(64); }
        __threadfence();
    }
    __syncthreads();
}

// Tile loader (512 threads): 128 rows x 256B -> smem, XOR-16B swizzle.
__device__ __forceinline__ void load_tile(u32 sbase,
                                          const __nv_bfloat16* gbase, int tid) {
    #pragma unroll
    for (int i = 0; i < 4; i++) {
        int id = i * NTHR + tid;
        int r  = id >> 4;
        int c  = id & 15;
        u32 dst = sbase + r * 256 + ((c ^ (r & 7)) << 4);
        cp16(dst, (const char*)gbase + r * 256 + c * 16);
    }
}

// ---------------------------------------------------------------------------
// ONE kernel, 128 blocks x 512 threads. 16 warps = 4 rg (32 rows) x 4 cg
// (32 cols): B fragments reused by 2 m-halves; 4 warps/SMSP hide latency.
// ---------------------------------------------------------------------------
__global__ __launch_bounds__(NTHR) void mono_kernel(const float* __restrict__ x,
                                                    const int* __restrict__ y,
                                                    float* __restrict__ out) {
    extern __shared__ __align__(1024) char smem[];
    __shared__ int ys[BCLS];
    __shared__ float red[NTHR];

    const int tid  = threadIdx.x;
    const int lane = tid & 31;
    const int w    = tid >> 5;
    const int b    = blockIdx.x;

    // ---------------- Phase 1: normalize 64 rows per block -----------------
    #pragma unroll
    for (int i = 0; i < 4; i++) {
        int row = b * 64 + w * 4 + i;
        float4 v = ((const float4*)(x + (size_t)row * DIM))[lane];
        float ss = v.x * v.x + v.y * v.y + v.z * v.z + v.w * v.w;
        #pragma unroll
        for (int o = 16; o; o >>= 1) ss += __shfl_xor_sync(0xffffffffu, ss, o);
        float inv = 1.0f / fmaxf(sqrtf(ss), 1e-12f);
        __nv_bfloat162 p0 = __floats2bfloat162_rn(v.x * inv, v.y * inv);
        __nv_bfloat162 p1 = __floats2bfloat162_rn(v.z * inv, v.w * inv);
        __nv_bfloat162* dst = (__nv_bfloat162*)(g_featb + (size_t)row * DIM);
        dst[lane * 2 + 0] = p0;
        dst[lane * 2 + 1] = p1;
    }

    grid_barrier();

    // ---------------- Phase 2: fused mainloop ------------------------------
    const u32 sA  = smem_u32(smem);
    const u32 sB0 = sA + 32768;
    const u32 sB1 = sA + 65536;
    const int rg  = w >> 2;                 // 0..3 (rows rg*32..+31)
    const int cg  = w & 3;                  // 0..3 (cols cg*32..+31)
    const int rowblk = b & 63;
    const int chalf  = b >> 6;
    const int myclass = __ldg(y + rowblk);

    load_tile(sA,  g_featb + (size_t)rowblk * RBLK * DIM, tid);
    load_tile(sB0, g_featb + (size_t)(chalf * CHALF) * DIM, tid);
    cp_commit();
    if (tid < BCLS) ys[tid] = y[tid];
    __syncthreads();

    // masks: col = cg*32 + n*8 + 2*(lane&3) + {0,1}; mod 64 -> (cg&1)*32 + ...
    const int l3 = lane & 3;
    float mf[4][2];
    #pragma unroll
    for (int n = 0; n < 4; n++) {
        int c0 = (cg & 1) * 32 + n * 8 + 2 * l3;
        mf[n][0] = (ys[c0]     == myclass) ? 1.0f : 0.0f;
        mf[n][1] = (ys[c0 + 1] == myclass) ? 1.0f : 0.0f;
    }

    // ldmatrix addressing
    const int lr = (lane & 7) | (((lane >> 3) & 1) << 3);
    const int hi = lane >> 4;
    const u32 kE = (u32)((lr & 6) << 4);
    const u32 ob = (u32)((hi ^ (lr & 1)) << 4);
    const u32 QA0 = sA + (u32)(rg * 32 + lr) * 256 + ob;       // m-half 0
    const u32 QA1 = QA0 + 16 * 256;                             // m-half 1
    const u32 cB  = (u32)(cg * 32 + lr) * 256 + ob;
    const u32 QB00 = sB0 + cB, QB01 = QB00 + 16 * 256;          // buf0 n-halves
    const u32 QB10 = sB1 + cB, QB11 = QB10 + 16 * 256;          // buf1 n-halves

    const float L2E = 1.4426950408889634f;
    float sa[2][2] = {{0.f, 0.f}, {0.f, 0.f}};
    float sp[2][2] = {{0.f, 0.f}, {0.f, 0.f}};

    for (int t = 0; t < NTILES; t++) {
        if (t + 1 < NTILES) {
            u32 sBnext = (t & 1) ? sB0 : sB1;
            load_tile(sBnext,
                      g_featb + (size_t)(chalf * CHALF + (t + 1) * CTILE) * DIM, tid);
            cp_commit();
            cp_wait<1>();
        } else {
            cp_wait<0>();
        }
        __syncthreads();

        float acc[2][4][4];
        #pragma unroll
        for (int m = 0; m < 2; m++)
            #pragma unroll
            for (int n = 0; n < 4; n++)
                #pragma unroll
                for (int q = 0; q < 4; q++) acc[m][n][q] = 0.f;

        const u32 B0 = (t & 1) ? QB10 : QB00;
        const u32 B1 = (t & 1) ? QB11 : QB01;

        #pragma unroll
        for (int s = 0; s < 8; s++) {
            const u32 off = ((u32)(s << 5)) ^ kE;
            u32 a00, a01, a02, a03, a10, a11, a12, a13;
            ldsm4(a00, a01, a02, a03, QA0 + off);
            ldsm4(a10, a11, a12, a13, QA1 + off);
            u32 b00, b01, b02, b03, b10, b11, b12, b13;
            ldsm4(b00, b01, b02, b03, B0 + off);
            ldsm4(b10, b11, b12, b13, B1 + off);
            mma16816(acc[0][0], a00, a01, a02, a03, b00, b02);
            mma16816(acc[1][0], a10, a11, a12, a13, b00, b02);
            mma16816(acc[0][1], a00, a01, a02, a03, b01, b03);
            mma16816(acc[1][1], a10, a11, a12, a13, b01, b03);
            mma16816(acc[0][2], a00, a01, a02, a03, b10, b12);
            mma16816(acc[1][2], a10, a11, a12, a13, b10, b12);
            mma16816(acc[0][3], a00, a01, a02, a03, b11, b13);
            mma16816(acc[1][3], a10, a11, a12, a13, b11, b13);
        }

        // epilogue: e = ex2(sim*L2E - L2E); masked accumulate
        #pragma unroll
        for (int m = 0; m < 2; m++) {
            #pragma unroll
            for (int n = 0; n < 4; n++) {
                float e0 = ex2f(fmaf(acc[m][n][0], L2E, -L2E));
                float e1 = ex2f(fmaf(acc[m][n][1], L2E, -L2E));
                float e2 = ex2f(fmaf(acc[m][n][2], L2E, -L2E));
                float e3 = ex2f(fmaf(acc[m][n][3], L2E, -L2E));
                sa[m][0] += e0 + e1;
                sa[m][1] += e2 + e3;
                sp[m][0] = fmaf(e0, mf[n][0], fmaf(e1, mf[n][1], sp[m][0]));
                sp[m][1] = fmaf(e2, mf[n][0], fmaf(e3, mf[n][1], sp[m][1]));
            }
        }
        __syncthreads();
    }

    // quad reduce + store (rows rg*32 + m*16 + h*8 + lane>>2)
    #pragma unroll
    for (int o = 1; o <= 2; o <<= 1) {
        #pragma unroll
        for (int m = 0; m < 2; m++) {
            #pragma unroll
            for (int h = 0; h < 2; h++) {
                sa[m][h] += __shfl_xor_sync(0xffffffffu, sa[m][h], o);
                sp[m][h] += __shfl_xor_sync(0xffffffffu, sp[m][h], o);
            }
        }
    }
    if (l3 == 0) {
        #pragma unroll
        for (int m = 0; m < 2; m++) {
            #pragma unroll
            for (int h = 0; h < 2; h++) {
                int r = rowblk * RBLK + rg * 32 + m * 16 + h * 8 + (lane >> 2);
                g_all[chalf][cg][r] = sa[m][h];
                g_pos[chalf][cg][r] = sp[m][h];
            }
        }
    }

    grid_barrier();

    // ---------------- Phase 3: finalize (block 0) --------------------------
    if (b == 0) {
        float s = 0.f;
        #pragma unroll
        for (int i = 0; i < 16; i++) {
            int r = i * NTHR + tid;
            float all = 0.f, pos = 0.f;
            #pragma unroll
            for (int c = 0; c < 4; c++) {
                all += g_all[0][c][r] + g_all[1][c][r];
                pos += g_pos[0][c][r] + g_pos[1][c][r];
            }
            s += -logf(pos / (all + 1e-8f) + 1e-8f);
        }
        red[tid] = s;
        __syncthreads();
        #pragma unroll
        for (int o = 256; o; o >>= 1) {
            if (tid < o) red[tid] += red[tid + o];
            __syncthreads();
        }
        if (tid == 0) out[0] = red[0] / (float)NROWS;
    }
}

extern "C" void kernel_launch(void* const* d_in, const int* in_sizes, int n_in,
                              void* d_out, int out_size) {
    const float* x = (const float*)d_in[0];   // [64,128,128] f32
    const int*   y = (const int*)d_in[1];     // [64] i32
    float* out = (float*)d_out;

    static int attr_set = 0;
    const int dyn_smem = 96 * 1024;
    if (!attr_set) {
        cudaFuncSetAttribute(mono_kernel,
                             cudaFuncAttributeMaxDynamicSharedMemorySize, dyn_smem);
        attr_set = 1;
    }

    mono_kernel<<<NBLK, NTHR, dyn_smem>>>(x, y, out);
}

// round 13
// speedup vs baseline: 1.4099x; 1.1538x over previous
#include <cuda_runtime.h>
#include <cuda_bf16.h>
#include <stdint.h>
#include <math.h>

typedef unsigned int u32;

// Fixed problem shape
#define NROWS 8192
#define DIM   128
#define BCLS  64
#define RBLK  128
#define NRB   64                       // 64 row blocks of 128 rows
#define NTILE_TOT 2080                 // upper-tri tile pairs incl diagonal
#define NBLK  128                      // co-resident (<= SM count)
#define NTHR  512
#define SLOTB 65536                    // A(32KB)+B(32KB) per slot

__device__ __align__(256) __nv_bfloat16 g_featb[NROWS * DIM];
__device__ float g_trA[NTILE_TOT][4][RBLK];   // row-side all, per cg
__device__ float g_trP[NTILE_TOT][4][RBLK];   // row-side pos
__device__ float g_tcA[NTILE_TOT][4][RBLK];   // col-side all, per rg
__device__ float g_tcP[NTILE_TOT][4][RBLK];   // col-side pos
__device__ float g_partial[NRB];
__device__ int g_ctr;                          // monotonic barrier counter

__device__ __forceinline__ int tri(int I) { return I * 64 - ((I * (I - 1)) >> 1); }

// ---------------------------------------------------------------------------
// PTX helpers
// ---------------------------------------------------------------------------
__device__ __forceinline__ u32 smem_u32(const void* p) {
    return (u32)__cvta_generic_to_shared(p);
}
__device__ __forceinline__ void cp16(u32 dst, const void* src) {
    asm volatile("cp.async.cg.shared.global [%0], [%1], 16;\n" :: "r"(dst), "l"(src));
}
__device__ __forceinline__ void cp_commit() {
    asm volatile("cp.async.commit_group;\n" ::: "memory");
}
template <int N>
__device__ __forceinline__ void cp_wait() {
    asm volatile("cp.async.wait_group %0;\n" :: "n"(N) : "memory");
}
__device__ __forceinline__ void ldsm4(u32& q0, u32& q1, u32& q2, u32& q3, u32 addr) {
    asm volatile("ldmatrix.sync.aligned.m8n8.x4.shared.b16 {%0,%1,%2,%3}, [%4];"
                 : "=r"(q0), "=r"(q1), "=r"(q2), "=r"(q3) : "r"(addr));
}
__device__ __forceinline__ void mma16816(float* dacc, u32 qa0, u32 qa1,
                                         u32 qa2, u32 qa3, u32 qb0, u32 qb1) {
    asm volatile("mma.sync.aligned.m16n8k16.row.col.f32.bf16.bf16.f32 "
                 "{%0,%1,%2,%3}, {%4,%5,%6,%7}, {%8,%9}, {%0,%1,%2,%3};"
                 : "+f"(dacc[0]), "+f"(dacc[1]), "+f"(dacc[2]), "+f"(dacc[3])
                 : "r"(qa0), "r"(qa1), "r"(qa2), "r"(qa3), "r"(qb0), "r"(qb1));
}
__device__ __forceinline__ float ex2f(float v) {
    float r;
    asm("ex2.approx.f32 %0, %1;" : "=f"(r) : "f"(v));
    return r;
}

// Re-entrant grid barrier (all NBLK blocks co-resident).
__device__ __forceinline__ void grid_barrier() {
    __syncthreads();
    if (threadIdx.x == 0) {
        __threadfence();
        int t = atomicAdd(&g_ctr, 1);
        int target = (t / NBLK + 1) * NBLK;
        while (atomicAdd(&g_ctr, 0) < target) { __nanosleep(64); }
        __threadfence();
    }
    __syncthreads();
}

// Tile loader (512 threads): 128 rows x 256B -> smem, XOR-16B swizzle.
__device__ __forceinline__ void load_tile(u32 sbase,
                                          const __nv_bfloat16* gbase, int tid) {
    #pragma unroll
    for (int i = 0; i < 4; i++) {
        int id = i * NTHR + tid;
        int r  = id >> 4;
        int c  = id & 15;
        u32 dst = sbase + r * 256 + ((c ^ (r & 7)) << 4);
        cp16(dst, (const char*)gbase + r * 256 + c * 16);
    }
}

// ---------------------------------------------------------------------------
// ONE persistent kernel. Phase1: normalize. Phase2: 2080 upper-tri tiles,
// row-side + col-side partials (E symmetric, exact). Phase3: assemble + loss.
// ---------------------------------------------------------------------------
__global__ __launch_bounds__(NTHR) void mono_sym_kernel(const float* __restrict__ x,
                                                        const int* __restrict__ y,
                                                        float* __restrict__ out) {
    extern __shared__ __align__(1024) char smem[];
    __shared__ int ysm[BCLS];
    __shared__ float red[RBLK];

    const int tid  = threadIdx.x;
    const int lane = tid & 31;
    const int w    = tid >> 5;
    const int b    = blockIdx.x;

    // ---------------- Phase 1: normalize 64 rows per block -----------------
    #pragma unroll
    for (int i = 0; i < 4; i++) {
        int row = b * 64 + w * 4 + i;
        float4 v = ((const float4*)(x + (size_t)row * DIM))[lane];
        float ss = v.x * v.x + v.y * v.y + v.z * v.z + v.w * v.w;
        #pragma unroll
        for (int o = 16; o; o >>= 1) ss += __shfl_xor_sync(0xffffffffu, ss, o);
        float inv = 1.0f / fmaxf(sqrtf(ss), 1e-12f);
        __nv_bfloat162 p0 = __floats2bfloat162_rn(v.x * inv, v.y * inv);
        __nv_bfloat162 p1 = __floats2bfloat162_rn(v.z * inv, v.w * inv);
        __nv_bfloat162* dst = (__nv_bfloat162*)(g_featb + (size_t)row * DIM);
        dst[lane * 2 + 0] = p0;
        dst[lane * 2 + 1] = p1;
    }
    if (tid < BCLS) ysm[tid] = y[tid];

    grid_barrier();

    // ---------------- Phase 2: symmetric fused mainloop --------------------
    const u32 s0 = smem_u32(smem);
    const u32 s1 = s0 + SLOTB;
    const int rg = w >> 2, cg = w & 3;
    const int l3 = lane & 3, lq = lane >> 2;

    const int cnt   = (b < 32) ? 17 : 16;
    const int start = (b < 32) ? b * 17 : 544 + (b - 32) * 16;

    int I = 0;
    while (tri(I + 1) <= start) I++;
    int J = start - tri(I) + I;
    int pI = I, pJ = J;
    pJ++; if (pJ == NRB) { pI++; pJ = pI; }     // prefetch iterator -> start+1

    // prologue: slot0 = tile(start) A+B
    load_tile(s0,         g_featb + (size_t)I * RBLK * DIM, tid);
    load_tile(s0 + 32768, g_featb + (size_t)J * RBLK * DIM, tid);
    cp_commit();

    // ldsm addressing
    const u32 lr = (u32)((lane & 7) | (((lane >> 3) & 1) << 3));
    const u32 hi = (u32)(lane >> 4);
    const u32 kE = (lr & 6) << 4;
    const u32 ob = (hi ^ (lr & 1)) << 4;
    u32 QA0s[2], QB0s[2];
    #pragma unroll
    for (int s = 0; s < 2; s++) {
        u32 base = s ? s1 : s0;
        QA0s[s] = base + (u32)(rg * 32 + lr) * 256 + ob;
        QB0s[s] = base + 32768 + (u32)(cg * 32 + lr) * 256 + ob;
    }

    const float L2E = 1.4426950408889634f;

    for (int t = 0; t < cnt; t++) {
        if (t + 1 < cnt) {
            u32 sl = ((t + 1) & 1) ? s1 : s0;
            load_tile(sl,         g_featb + (size_t)pI * RBLK * DIM, tid);
            load_tile(sl + 32768, g_featb + (size_t)pJ * RBLK * DIM, tid);
            cp_commit();
            pJ++; if (pJ == NRB) { pI++; pJ = pI; }
            cp_wait<1>();
        } else {
            cp_wait<0>();
        }
        __syncthreads();

        const int nt   = start + t;
        const int clsI = ysm[I];
        const int clsJ = ysm[J];
        const bool diag = (I == J);

        // masks
        float mf[4][2];
        #pragma unroll
        for (int n = 0; n < 4; n++) {
            int c0 = (cg & 1) * 32 + n * 8 + 2 * l3;
            mf[n][0] = (ysm[c0]     == clsI) ? 1.0f : 0.0f;
            mf[n][1] = (ysm[c0 + 1] == clsI) ? 1.0f : 0.0f;
        }
        float mc[2][2];
        #pragma unroll
        for (int m = 0; m < 2; m++) {
            #pragma unroll
            for (int h = 0; h < 2; h++)
                mc[m][h] = (clsJ == ysm[(rg & 1) * 32 + m * 16 + h * 8 + lq]) ? 1.0f : 0.0f;
        }

        // MMA
        float acc[2][4][4];
        #pragma unroll
        for (int m = 0; m < 2; m++)
            #pragma unroll
            for (int n = 0; n < 4; n++)
                #pragma unroll
                for (int q = 0; q < 4; q++) acc[m][n][q] = 0.f;

        const u32 QA0 = QA0s[t & 1], QA1 = QA0 + 4096;
        const u32 B0  = QB0s[t & 1], B1  = B0 + 4096;

        #pragma unroll
        for (int s = 0; s < 8; s++) {
            const u32 off = ((u32)(s << 5)) ^ kE;
            u32 a00, a01, a02, a03, a10, a11, a12, a13;
            ldsm4(a00, a01, a02, a03, QA0 + off);
            ldsm4(a10, a11, a12, a13, QA1 + off);
            u32 b00, b01, b02, b03, b10, b11, b12, b13;
            ldsm4(b00, b01, b02, b03, B0 + off);
            ldsm4(b10, b11, b12, b13, B1 + off);
            mma16816(acc[0][0], a00, a01, a02, a03, b00, b02);
            mma16816(acc[1][0], a10, a11, a12, a13, b00, b02);
            mma16816(acc[0][1], a00, a01, a02, a03, b01, b03);
            mma16816(acc[1][1], a10, a11, a12, a13, b01, b03);
            mma16816(acc[0][2], a00, a01, a02, a03, b10, b12);
            mma16816(acc[1][2], a10, a11, a12, a13, b10, b12);
            mma16816(acc[0][3], a00, a01, a02, a03, b11, b13);
            mma16816(acc[1][3], a10, a11, a12, a13, b11, b13);
        }

        // epilogue: row-side + col-side accumulation
        float ra[2][2] = {{0.f,0.f},{0.f,0.f}}, rp[2][2] = {{0.f,0.f},{0.f,0.f}};
        float cA[4][2] = {{0.f,0.f},{0.f,0.f},{0.f,0.f},{0.f,0.f}};
        float cP[4][2] = {{0.f,0.f},{0.f,0.f},{0.f,0.f},{0.f,0.f}};
        #pragma unroll
        for (int m = 0; m < 2; m++) {
            #pragma unroll
            for (int n = 0; n < 4; n++) {
                float e0 = ex2f(fmaf(acc[m][n][0], L2E, -L2E));
                float e1 = ex2f(fmaf(acc[m][n][1], L2E, -L2E));
                float e2 = ex2f(fmaf(acc[m][n][2], L2E, -L2E));
                float e3 = ex2f(fmaf(acc[m][n][3], L2E, -L2E));
                ra[m][0] += e0 + e1;
                ra[m][1] += e2 + e3;
                rp[m][0] = fmaf(e0, mf[n][0], fmaf(e1, mf[n][1], rp[m][0]));
                rp[m][1] = fmaf(e2, mf[n][0], fmaf(e3, mf[n][1], rp[m][1]));
                cA[n][0] += e0 + e2;
                cA[n][1] += e1 + e3;
                cP[n][0] = fmaf(e0, mc[m][0], fmaf(e2, mc[m][1], cP[n][0]));
                cP[n][1] = fmaf(e1, mc[m][0], fmaf(e3, mc[m][1], cP[n][1]));
            }
        }

        // row-side flush: quad reduce, l3==0 stores
        #pragma unroll
        for (int o = 1; o <= 2; o <<= 1) {
            #pragma unroll
            for (int m = 0; m < 2; m++) {
                #pragma unroll
                for (int h = 0; h < 2; h++) {
                    ra[m][h] += __shfl_xor_sync(0xffffffffu, ra[m][h], o);
                    rp[m][h] += __shfl_xor_sync(0xffffffffu, rp[m][h], o);
                }
            }
        }
        if (l3 == 0) {
            #pragma unroll
            for (int m = 0; m < 2; m++) {
                #pragma unroll
                for (int h = 0; h < 2; h++) {
                    int r = rg * 32 + m * 16 + h * 8 + lq;
                    g_trA[nt][cg][r] = ra[m][h];
                    g_trP[nt][cg][r] = rp[m][h];
                }
            }
        }

        // col-side flush (off-diagonal): reduce over rows (xor 4,8,16), lanes 0..3 store
        if (!diag) {
            #pragma unroll
            for (int o = 4; o <= 16; o <<= 1) {
                #pragma unroll
                for (int n = 0; n < 4; n++) {
                    #pragma unroll
                    for (int bb = 0; bb < 2; bb++) {
                        cA[n][bb] += __shfl_xor_sync(0xffffffffu, cA[n][bb], o);
                        cP[n][bb] += __shfl_xor_sync(0xffffffffu, cP[n][bb], o);
                    }
                }
            }
            if (lane < 4) {
                #pragma unroll
                for (int n = 0; n < 4; n++) {
                    #pragma unroll
                    for (int bb = 0; bb < 2; bb++) {
                        int jl = cg * 32 + n * 8 + 2 * lane + bb;
                        g_tcA[nt][rg][jl] = cA[n][bb];
                        g_tcP[nt][rg][jl] = cP[n][bb];
                    }
                }
            }
        }

        __syncthreads();
        J++; if (J == NRB) { I++; J = I; }
    }

    grid_barrier();

    // ---------------- Phase 3: assemble rows + per-row loss ----------------
    if (b < NRB) {
        const int rb = b;
        const int il = tid >> 2;          // local row 0..127
        const int p  = tid & 3;           // partial index
        float all = 0.f, pos = 0.f;
        const int base = tri(rb);
        for (int k = p; k <= NRB - 1 - rb; k += 4) {
            int n = base + k;
            #pragma unroll
            for (int c = 0; c < 4; c++) {
                all += g_trA[n][c][il];
                pos += g_trP[n][c][il];
            }
        }
        for (int I2 = p; I2 < rb; I2 += 4) {
            int n = tri(I2) + rb - I2;
            #pragma unroll
            for (int g = 0; g < 4; g++) {
                all += g_tcA[n][g][il];
                pos += g_tcP[n][g][il];
            }
        }
        all += __shfl_xor_sync(0xffffffffu, all, 1);
        all += __shfl_xor_sync(0xffffffffu, all, 2);
        pos += __shfl_xor_sync(0xffffffffu, pos, 1);
        pos += __shfl_xor_sync(0xffffffffu, pos, 2);
        if (p == 0) red[il] = -logf(pos / (all + 1e-8f) + 1e-8f);
        __syncthreads();
        #pragma unroll
        for (int o = 64; o; o >>= 1) {
            if (tid < o) red[tid] += red[tid + o];
            __syncthreads();
        }
        if (tid == 0) g_partial[rb] = red[0];
    }

    grid_barrier();

    if (b == 0 && tid == 0) {
        float s = 0.f;
        #pragma unroll
        for (int i = 0; i < NRB; i++) s += g_partial[i];
        out[0] = s / (float)NROWS;
    }
}

extern "C" void kernel_launch(void* const* d_in, const int* in_sizes, int n_in,
                              void* d_out, int out_size) {
    const float* x = (const float*)d_in[0];   // [64,128,128] f32
    const int*   y = (const int*)d_in[1];     // [64] i32
    float* out = (float*)d_out;

    static int attr_set = 0;
    const int dyn_smem = 2 * SLOTB;            // 128 KB
    if (!attr_set) {
        cudaFuncSetAttribute(mono_sym_kernel,
                             cudaFuncAttributeMaxDynamicSharedMemorySize, dyn_smem);
        attr_set = 1;
    }

    mono_sym_kernel<<<NBLK, NTHR, dyn_smem>>>(x, y, out);
}

// round 15
// speedup vs baseline: 1.6047x; 1.1382x over previous
#include <cuda_runtime.h>
#include <cuda_bf16.h>
#include <stdint.h>
#include <math.h>

typedef unsigned int u32;

// Fixed problem shape
#define NROWS 8192
#define DIM   128
#define BCLS  64
#define RBLK  128
#define NRB   64
#define NTILE_TOT 2080
#define NBLK  128
#define NTHR  512

__device__ __align__(256) __nv_bfloat16 g_featb[NROWS * DIM];
__device__ float g_rowA[NRB][4][4][RBLK];     // [rowblk][sub][cg][row]  (131072 floats)
__device__ float g_rowP[NRB][4][4][RBLK];
__device__ float g_tcA[NTILE_TOT][4][RBLK];   // col-side, per rg
__device__ float g_tcP[NTILE_TOT][4][RBLK];
__device__ float g_partial[NRB];
__device__ int g_ctr;

__device__ __forceinline__ int tri(int I) { return I * 64 - ((I * (I - 1)) >> 1); }

// ---------------------------------------------------------------------------
// PTX helpers
// ---------------------------------------------------------------------------
__device__ __forceinline__ u32 smem_u32(const void* p) {
    return (u32)__cvta_generic_to_shared(p);
}
__device__ __forceinline__ void cp16(u32 dst, const void* src) {
    asm volatile("cp.async.cg.shared.global [%0], [%1], 16;\n" :: "r"(dst), "l"(src));
}
__device__ __forceinline__ void cp_commit() {
    asm volatile("cp.async.commit_group;\n" ::: "memory");
}
template <int N>
__device__ __forceinline__ void cp_wait() {
    asm volatile("cp.async.wait_group %0;\n" :: "n"(N) : "memory");
}
__device__ __forceinline__ void ldsm4(u32& q0, u32& q1, u32& q2, u32& q3, u32 addr) {
    asm volatile("ldmatrix.sync.aligned.m8n8.x4.shared.b16 {%0,%1,%2,%3}, [%4];"
                 : "=r"(q0), "=r"(q1), "=r"(q2), "=r"(q3) : "r"(addr));
}
__device__ __forceinline__ void mma16816(float* dacc, u32 qa0, u32 qa1,
                                         u32 qa2, u32 qa3, u32 qb0, u32 qb1) {
    asm volatile("mma.sync.aligned.m16n8k16.row.col.f32.bf16.bf16.f32 "
                 "{%0,%1,%2,%3}, {%4,%5,%6,%7}, {%8,%9}, {%0,%1,%2,%3};"
                 : "+f"(dacc[0]), "+f"(dacc[1]), "+f"(dacc[2]), "+f"(dacc[3])
                 : "r"(qa0), "r"(qa1), "r"(qa2), "r"(qa3), "r"(qb0), "r"(qb1));
}
__device__ __forceinline__ float ex2f(float v) {
    float r;
    asm("ex2.approx.f32 %0, %1;" : "=f"(r) : "f"(v));
    return r;
}

// Re-entrant grid barrier (all NBLK blocks co-resident).
__device__ __forceinline__ void grid_barrier() {
    __syncthreads();
    if (threadIdx.x == 0) {
        __threadfence();
        int t = atomicAdd(&g_ctr, 1);
        int target = (t / NBLK + 1) * NBLK;
        while (atomicAdd(&g_ctr, 0) < target) { __nanosleep(64); }
        __threadfence();
    }
    __syncthreads();
}

// Tile loader: 128 rows x 256B -> smem, XOR-16B swizzle (512 threads).
__device__ __forceinline__ void load_tile(u32 sbase,
                                          const __nv_bfloat16* gbase, int tid) {
    #pragma unroll
    for (int i = 0; i < 4; i++) {
        int id = i * NTHR + tid;
        int r  = id >> 4;
        int c  = id & 15;
        u32 dst = sbase + r * 256 + ((c ^ (r & 7)) << 4);
        cp16(dst, (const char*)gbase + r * 256 + c * 16);
    }
}

// ---------------------------------------------------------------------------
// ONE persistent kernel, strip-decomposed symmetric tiles.
// Pair p = b>>2: rows I1=p (64-p tiles) + I2=63-p (p+1 tiles) = 65 tiles.
// Block sub = b&3 takes 17/16/16/16 consecutive tiles. B buffers indexed by
// local idx parity (prologue -> buf0). A reloaded once if segment crosses n1.
// ---------------------------------------------------------------------------
__global__ __launch_bounds__(NTHR) void mono_strip_kernel(const float* __restrict__ x,
                                                          const int* __restrict__ y,
                                                          float* __restrict__ out) {
    extern __shared__ __align__(1024) char smem[];
    __shared__ int ysm[BCLS];
    __shared__ float red[RBLK];

    const int tid  = threadIdx.x;
    const int lane = tid & 31;
    const int w    = tid >> 5;
    const int b    = blockIdx.x;

    // ---------------- Phase 1: normalize 64 rows + zero row scratch --------
    #pragma unroll
    for (int i = 0; i < 4; i++) {
        int row = b * 64 + w * 4 + i;
        float4 v = ((const float4*)(x + (size_t)row * DIM))[lane];
        float ss = v.x * v.x + v.y * v.y + v.z * v.z + v.w * v.w;
        #pragma unroll
        for (int o = 16; o; o >>= 1) ss += __shfl_xor_sync(0xffffffffu, ss, o);
        float inv = 1.0f / fmaxf(sqrtf(ss), 1e-12f);
        __nv_bfloat162 p0 = __floats2bfloat162_rn(v.x * inv, v.y * inv);
        __nv_bfloat162 p1 = __floats2bfloat162_rn(v.z * inv, v.w * inv);
        __nv_bfloat162* dst = (__nv_bfloat162*)(g_featb + (size_t)row * DIM);
        dst[lane * 2 + 0] = p0;
        dst[lane * 2 + 1] = p1;
    }
    {   // zero g_rowA/g_rowP: 131072 floats each -> 1024 per block per array
        float* za = &g_rowA[0][0][0][0];
        float* zp = &g_rowP[0][0][0][0];
        za[b * 1024 + tid]       = 0.f;
        za[b * 1024 + 512 + tid] = 0.f;
        zp[b * 1024 + tid]       = 0.f;
        zp[b * 1024 + 512 + tid] = 0.f;
    }
    if (tid < BCLS) ysm[tid] = y[tid];

    grid_barrier();

    // ---------------- Phase 2: strip mainloop ------------------------------
    const u32 sA  = smem_u32(smem);
    const u32 sB0 = sA + 32768;
    const u32 sB1 = sA + 65536;
    const int rg = w >> 2, cg = w & 3;
    const int l3 = lane & 3, lq = lane >> 2;

    const int p   = b >> 2;
    const int sub = b & 3;
    const int I1 = p, I2 = 63 - p;
    const int n1 = 64 - p;                       // tiles in row I1
    const int k0 = (sub == 0) ? 0 : sub * 16 + 1;
    const int k1 = k0 + ((sub == 0) ? 17 : 16);

    // k -> (I, J)
    #define K_I(k) ((k) < n1 ? I1 : I2)
    #define K_J(k) ((k) < n1 ? I1 + (k) : I2 + ((k) - n1))

    // prologue: A(segment start) + B(k0) -> buf0 (one group)
    load_tile(sA, g_featb + (size_t)K_I(k0) * RBLK * DIM, tid);
    load_tile(sB0, g_featb + (size_t)K_J(k0) * RBLK * DIM, tid);
    cp_commit();

    // ldsm addressing
    const u32 lr = (u32)((lane & 7) | (((lane >> 3) & 1) << 3));
    const u32 hi = (u32)(lane >> 4);
    const u32 kE = (lr & 6) << 4;
    const u32 ob = (hi ^ (lr & 1)) << 4;
    const u32 QA0 = sA + (u32)(rg * 32 + lr) * 256 + ob;
    const u32 QA1 = QA0 + 4096;
    const u32 cBo = (u32)(cg * 32 + lr) * 256 + ob;

    const float L2E = 1.4426950408889634f;
    float ra[2][2] = {{0.f,0.f},{0.f,0.f}}, rp[2][2] = {{0.f,0.f},{0.f,0.f}};

    int idx = 0;
    for (int t = k0; t < k1; t++, idx++) {
        // pipeline: prefetch next / reload A at segment boundary
        if (t == n1 && t > k0) {
            // A changes to I2 for THIS tile: load it now (old A reads done
            // at previous iteration's trailing __syncthreads)
            load_tile(sA, g_featb + (size_t)I2 * RBLK * DIM, tid);
            if (t + 1 < k1)
                load_tile((idx & 1) ? sB0 : sB1,   // buf[(idx+1)&1]
                          g_featb + (size_t)K_J(t + 1) * RBLK * DIM, tid);
            cp_commit();
            cp_wait<0>();
        } else if (t + 1 < k1) {
            load_tile((idx & 1) ? sB0 : sB1,       // buf[(idx+1)&1]
                      g_featb + (size_t)K_J(t + 1) * RBLK * DIM, tid);
            cp_commit();
            cp_wait<1>();
        } else {
            cp_wait<0>();
        }
        __syncthreads();

        const int I = K_I(t);
        const int J = K_J(t);
        const int nt = tri(I) + (J - I);
        const int clsI = ysm[I];
        const int clsJ = ysm[J];
        const bool diag = (I == J);

        // masks
        float mf[4][2];
        #pragma unroll
        for (int n = 0; n < 4; n++) {
            int c0 = (cg & 1) * 32 + n * 8 + 2 * l3;
            mf[n][0] = (ysm[c0]     == clsI) ? 1.0f : 0.0f;
            mf[n][1] = (ysm[c0 + 1] == clsI) ? 1.0f : 0.0f;
        }
        float mc[2][2];
        #pragma unroll
        for (int m = 0; m < 2; m++) {
            #pragma unroll
            for (int h = 0; h < 2; h++)
                mc[m][h] = (clsJ == ysm[(rg & 1) * 32 + m * 16 + h * 8 + lq]) ? 1.0f : 0.0f;
        }

        // MMA
        float acc[2][4][4];
        #pragma unroll
        for (int m = 0; m < 2; m++)
            #pragma unroll
            for (int n = 0; n < 4; n++)
                #pragma unroll
                for (int q = 0; q < 4; q++) acc[m][n][q] = 0.f;

        const u32 B0 = ((idx & 1) ? sB1 : sB0) + cBo;
        const u32 B1 = B0 + 4096;

        #pragma unroll
        for (int s = 0; s < 8; s++) {
            const u32 off = ((u32)(s << 5)) ^ kE;
            u32 a00, a01, a02, a03, a10, a11, a12, a13;
            ldsm4(a00, a01, a02, a03, QA0 + off);
            ldsm4(a10, a11, a12, a13, QA1 + off);
            u32 b00, b01, b02, b03, b10, b11, b12, b13;
            ldsm4(b00, b01, b02, b03, B0 + off);
            ldsm4(b10, b11, b12, b13, B1 + off);
            mma16816(acc[0][0], a00, a01, a02, a03, b00, b02);
            mma16816(acc[1][0], a10, a11, a12, a13, b00, b02);
            mma16816(acc[0][1], a00, a01, a02, a03, b01, b03);
            mma16816(acc[1][1], a10, a11, a12, a13, b01, b03);
            mma16816(acc[0][2], a00, a01, a02, a03, b10, b12);
            mma16816(acc[1][2], a10, a11, a12, a13, b10, b12);
            mma16816(acc[0][3], a00, a01, a02, a03, b11, b13);
            mma16816(acc[1][3], a10, a11, a12, a13, b11, b13);
        }

        // epilogue: exp + row-side accumulate (registers) + col-side partials
        float cA[4][2] = {{0.f,0.f},{0.f,0.f},{0.f,0.f},{0.f,0.f}};
        float cP[4][2] = {{0.f,0.f},{0.f,0.f},{0.f,0.f},{0.f,0.f}};
        #pragma unroll
        for (int m = 0; m < 2; m++) {
            #pragma unroll
            for (int n = 0; n < 4; n++) {
                float e0 = ex2f(fmaf(acc[m][n][0], L2E, -L2E));
                float e1 = ex2f(fmaf(acc[m][n][1], L2E, -L2E));
                float e2 = ex2f(fmaf(acc[m][n][2], L2E, -L2E));
                float e3 = ex2f(fmaf(acc[m][n][3], L2E, -L2E));
                ra[m][0] += e0 + e1;
                ra[m][1] += e2 + e3;
                rp[m][0] = fmaf(e0, mf[n][0], fmaf(e1, mf[n][1], rp[m][0]));
                rp[m][1] = fmaf(e2, mf[n][0], fmaf(e3, mf[n][1], rp[m][1]));
                cA[n][0] += e0 + e2;
                cA[n][1] += e1 + e3;
                cP[n][0] = fmaf(e0, mc[m][0], fmaf(e2, mc[m][1], cP[n][0]));
                cP[n][1] = fmaf(e1, mc[m][0], fmaf(e3, mc[m][1], cP[n][1]));
            }
        }

        // col-side flush (off-diagonal tiles)
        if (!diag) {
            #pragma unroll
            for (int o = 4; o <= 16; o <<= 1) {
                #pragma unroll
                for (int n = 0; n < 4; n++) {
                    #pragma unroll
                    for (int bb = 0; bb < 2; bb++) {
                        cA[n][bb] += __shfl_xor_sync(0xffffffffu, cA[n][bb], o);
                        cP[n][bb] += __shfl_xor_sync(0xffffffffu, cP[n][bb], o);
                    }
                }
            }
            if (lane < 4) {
                #pragma unroll
                for (int n = 0; n < 4; n++) {
                    #pragma unroll
                    for (int bb = 0; bb < 2; bb++) {
                        int jl = cg * 32 + n * 8 + 2 * lane + bb;
                        g_tcA[nt][rg][jl] = cA[n][bb];
                        g_tcP[nt][rg][jl] = cP[n][bb];
                    }
                }
            }
        }

        // row-side flush at end of I-segment
        const bool flushNow = (t == k1 - 1) || (t == n1 - 1);
        if (flushNow) {
            #pragma unroll
            for (int o = 1; o <= 2; o <<= 1) {
                #pragma unroll
                for (int m = 0; m < 2; m++) {
                    #pragma unroll
                    for (int h = 0; h < 2; h++) {
                        ra[m][h] += __shfl_xor_sync(0xffffffffu, ra[m][h], o);
                        rp[m][h] += __shfl_xor_sync(0xffffffffu, rp[m][h], o);
                    }
                }
            }
            if (l3 == 0) {
                #pragma unroll
                for (int m = 0; m < 2; m++) {
                    #pragma unroll
                    for (int h = 0; h < 2; h++) {
                        int r = rg * 32 + m * 16 + h * 8 + lq;
                        g_rowA[I][sub][cg][r] = ra[m][h];
                        g_rowP[I][sub][cg][r] = rp[m][h];
                    }
                }
            }
            #pragma unroll
            for (int m = 0; m < 2; m++) {
                #pragma unroll
                for (int h = 0; h < 2; h++) { ra[m][h] = 0.f; rp[m][h] = 0.f; }
            }
        }
        __syncthreads();
    }
    #undef K_I
    #undef K_J

    grid_barrier();

    // ---------------- Phase 3: assemble rows + per-row loss ----------------
    if (b < NRB) {
        const int rb = b;
        const int il = tid >> 2;
        const int pp = tid & 3;
        float all = 0.f, pos = 0.f;
        // row-side: slot sub == pp
        #pragma unroll
        for (int c = 0; c < 4; c++) {
            all += g_rowA[rb][pp][c][il];
            pos += g_rowP[rb][pp][c][il];
        }
        // col-side: tiles (I, rb), I < rb
        for (int I2x = pp; I2x < rb; I2x += 4) {
            int n = tri(I2x) + rb - I2x;
            #pragma unroll
            for (int g = 0; g < 4; g++) {
                all += g_tcA[n][g][il];
                pos += g_tcP[n][g][il];
            }
        }
        all += __shfl_xor_sync(0xffffffffu, all, 1);
        all += __shfl_xor_sync(0xffffffffu, all, 2);
        pos += __shfl_xor_sync(0xffffffffu, pos, 1);
        pos += __shfl_xor_sync(0xffffffffu, pos, 2);
        if (pp == 0) red[il] = -logf(pos / (all + 1e-8f) + 1e-8f);
        __syncthreads();
        #pragma unroll
        for (int o = 64; o; o >>= 1) {
            if (tid < o) red[tid] += red[tid + o];
            __syncthreads();
        }
        if (tid == 0) g_partial[rb] = red[0];
    }

    grid_barrier();

    if (b == 0 && tid == 0) {
        float s = 0.f;
        #pragma unroll
        for (int i = 0; i < NRB; i++) s += g_partial[i];
        out[0] = s / (float)NROWS;
    }
}

extern "C" void kernel_launch(void* const* d_in, const int* in_sizes, int n_in,
                              void* d_out, int out_size) {
    const float* x = (const float*)d_in[0];   // [64,128,128] f32
    const int*   y = (const int*)d_in[1];     // [64] i32
    float* out = (float*)d_out;

    static int attr_set = 0;
    const int dyn_smem = 96 * 1024;
    if (!attr_set) {
        cudaFuncSetAttribute(mono_strip_kernel,
                             cudaFuncAttributeMaxDynamicSharedMemorySize, dyn_smem);
        attr_set = 1;
    }

    mono_strip_kernel<<<NBLK, NTHR, dyn_smem>>>(x, y, out);
}